// round 15
// baseline (speedup 1.0000x reference)
#include <cuda_runtime.h>
#include <cstdint>

#define NN 50000
#define EE 800000
#define KDIM 128
#define DHID 128
#define DOUT 64
#define NB   ((NN + 255) / 256)   // 196 scan blocks

// ---------------- scratch (device globals; no allocs allowed) ----------------
// g_deg relies on static zero-init for the FIRST call; every launch re-zeroes
// it at the tail of agg_epi2 (after its last read in scanA).
__device__ int g_deg[NN];
__device__ int g_rowstart[NN + 1];
__device__ int g_cursor[NN];
__device__ int g_esrc[EE];
__device__ int g_bsum[NB];

__device__ float g_zl[NN * DHID];  // x @ W_l1  (gets aggregated into h)
__device__ float g_zr[NN * DHID];  // x @ W_r1  (self term)
__device__ float g_ul[NN * DOUT];  // h @ W_l2  (gets aggregated)
__device__ float g_ur[NN * DOUT];  // h @ W_r2  (self term)
// NOTE: g_h eliminated — h lives only in gemm2's smem A-tile.

// ---------------- per-block edge dtype detection (no global state) ----------------
template <int THREADS, int PER>
__device__ __forceinline__ bool detect_is64(const int* __restrict__ ei32, int* s_nz) {
    if (threadIdx.x == 0) *s_nz = 0;
    __syncthreads();
    bool nz = false;
#pragma unroll
    for (int p = 0; p < PER; p++) {
        int i = threadIdx.x + p * THREADS;      // i in [0, 1024)
        nz |= (ei32[2 * i + 1] != 0);
    }
    if (__ballot_sync(0xffffffffu, nz) && (threadIdx.x & 31) == 0) *s_nz = 1;
    __syncthreads();
    return (*s_nz == 0);
}

__device__ __forceinline__ int edge_at(const void* ei, bool is64, long long idx) {
    return is64 ? (int)((const long long*)ei)[idx] : ((const int*)ei)[idx];
}

// ---------------- tf32 helpers ----------------
__device__ __forceinline__ float tf32_hi(float v) {
    uint32_t r;
    asm("cvt.rna.tf32.f32 %0, %1;" : "=r"(r) : "f"(v));
    return __uint_as_float(r);
}

__device__ __forceinline__ void mma_tf32(float d[4], const uint32_t a[4], const uint32_t b[2]) {
    asm volatile(
        "mma.sync.aligned.m16n8k8.row.col.f32.tf32.tf32.f32 "
        "{%0,%1,%2,%3}, {%4,%5,%6,%7}, {%8,%9}, {%0,%1,%2,%3};\n"
        : "+f"(d[0]), "+f"(d[1]), "+f"(d[2]), "+f"(d[3])
        : "r"(a[0]), "r"(a[1]), "r"(a[2]), "r"(a[3]),
          "r"(b[0]), "r"(b[1]));
}

// ---------------- shared GEMM compute: As/Bs smem-resident, full K ----------------
// MMA + epilogue over As[BM][ASTR], Bs[KDIM][BSTR]; outputs split C1|C2.
template <int BN>
__device__ __forceinline__
void gemm_mma_epilogue(int row0, const float* As, const float* Bs,
                       float* __restrict__ C1, float* __restrict__ C2) {
    constexpr int HALF = BN / 2;
    constexpr int WN = BN / 4;
    constexpr int NT = WN / 8;
    constexpr int ASTR = KDIM + 8;
    constexpr int BSTR = BN + 8;

    const int tid = threadIdx.x;
    const int wid = tid >> 5, lane = tid & 31;
    const int gq = lane >> 2, tg = lane & 3;
    const int warp_m = wid & 3;
    const int warp_n = wid >> 2;

    float acc[2][NT][4];
#pragma unroll
    for (int mt = 0; mt < 2; mt++)
#pragma unroll
        for (int nt = 0; nt < NT; nt++)
#pragma unroll
            for (int r = 0; r < 4; r++) acc[mt][nt][r] = 0.0f;

#pragma unroll 1
    for (int ks = 0; ks < KDIM / 8; ks++) {
        const int kk = ks * 8;
        uint32_t ah[2][4], al[2][4];
#pragma unroll
        for (int mt = 0; mt < 2; mt++) {
            int r = warp_m * 32 + mt * 16 + gq;
            float f0 = As[(r    ) * ASTR + kk + tg];
            float f1 = As[(r + 8) * ASTR + kk + tg];
            float f2 = As[(r    ) * ASTR + kk + tg + 4];
            float f3 = As[(r + 8) * ASTR + kk + tg + 4];
            float h0 = tf32_hi(f0), h1 = tf32_hi(f1), h2 = tf32_hi(f2), h3 = tf32_hi(f3);
            ah[mt][0] = __float_as_uint(h0); al[mt][0] = __float_as_uint(f0 - h0);
            ah[mt][1] = __float_as_uint(h1); al[mt][1] = __float_as_uint(f1 - h1);
            ah[mt][2] = __float_as_uint(h2); al[mt][2] = __float_as_uint(f2 - h2);
            ah[mt][3] = __float_as_uint(h3); al[mt][3] = __float_as_uint(f3 - h3);
        }
#pragma unroll
        for (int nt = 0; nt < NT; nt++) {
            int c = warp_n * WN + nt * 8 + gq;
            float g0 = Bs[(kk + tg    ) * BSTR + c];
            float g1 = Bs[(kk + tg + 4) * BSTR + c];
            float h0 = tf32_hi(g0), h1 = tf32_hi(g1);
            uint32_t bh[2], bl[2];
            bh[0] = __float_as_uint(h0); bl[0] = __float_as_uint(g0 - h0);
            bh[1] = __float_as_uint(h1); bl[1] = __float_as_uint(g1 - h1);
#pragma unroll
            for (int mt = 0; mt < 2; mt++) {
                mma_tf32(acc[mt][nt], al[mt], bh);  // lo*hi
                mma_tf32(acc[mt][nt], ah[mt], bl);  // hi*lo
                mma_tf32(acc[mt][nt], ah[mt], bh);  // hi*hi
            }
        }
    }

#pragma unroll
    for (int mt = 0; mt < 2; mt++) {
        int r = row0 + warp_m * 32 + mt * 16 + gq;
#pragma unroll
        for (int nt = 0; nt < NT; nt++) {
            int c = warp_n * WN + nt * 8 + 2 * tg;
            float* Cp = (c < HALF) ? C1 : C2;
            int cc = (c < HALF) ? c : c - HALF;
            if (r < NN) {
                float2 v = make_float2(acc[mt][nt][0], acc[mt][nt][1]);
                *(float2*)&Cp[r * HALF + cc] = v;
            }
            if (r + 8 < NN) {
                float2 v = make_float2(acc[mt][nt][2], acc[mt][nt][3]);
                *(float2*)&Cp[(r + 8) * HALF + cc] = v;
            }
        }
    }
}

// B-fill helper: Bs[KDIM][BN+8] from B1|B2 halves.
template <int BN, int THREADS>
__device__ __forceinline__
void fill_B(float* Bs, const float* __restrict__ B1, const float* __restrict__ B2) {
    constexpr int HALF = BN / 2;
    constexpr int BSTR = BN + 8;
    const int tid = threadIdx.x;
#pragma unroll
    for (int p = 0; p < (KDIM * BN) / (THREADS * 4); p++) {
        int idx = (p * THREADS + tid) * 4;
        int k = idx / BN;
        int n = idx % BN;
        const float* src = (n < HALF) ? &B1[k * HALF + n] : &B2[k * HALF + (n - HALF)];
        *(float4*)&Bs[k * BSTR + n] = *(const float4*)src;
    }
}

#define SMEM_F1 ((128 * (KDIM + 8) + KDIM * (256 + 8)) * 4)   // 204800 B
#define SMEM_F2 ((128 * (KDIM + 8) + KDIM * (128 + 8)) * 4)   // 139264 B

#define GEMM_GRID ((NN + 127) / 128)          // 391 gemm blocks
#define HIST_BLOCKS 128
#define K1_GRID (GEMM_GRID + HIST_BLOCKS)     // 519; every 4th block (bx%4==3, bx<512) is hist

// ---------------- K1: layer-1 fused GEMM + degree histogram (role-split) ----------------
__global__ __launch_bounds__(512) void gemm1_hist_kernel(const float* __restrict__ x,
                                                         const float* __restrict__ Wl1,
                                                         const float* __restrict__ Wr1,
                                                         const void* __restrict__ ei) {
    const int bx = blockIdx.x;
    const bool is_hist = (bx < 512) && ((bx & 3) == 3);
    if (is_hist) {
        __shared__ int s_nz;
        bool is64 = detect_is64<512, 2>((const int*)ei, &s_nz);
        const int hid = bx >> 2;                         // 0..127
        const int stride = HIST_BLOCKS * 512;
        for (int e = hid * 512 + threadIdx.x; e < EE; e += stride) {
            int d = edge_at(ei, is64, (long long)EE + e);
            if ((unsigned)d < NN) atomicAdd(&g_deg[d], 1);
        }
    } else {
        int gid = (bx < 512) ? (bx - ((bx + 1) >> 2)) : (bx - HIST_BLOCKS);
        constexpr int ASTR = KDIM + 8;
        extern __shared__ float smem[];
        float* As = smem;
        float* Bs = smem + 128 * ASTR;
        const int row0 = gid * 128;
        const int tid = threadIdx.x;
        // A fill: x rows
#pragma unroll
        for (int p = 0; p < (128 * KDIM) / (512 * 4); p++) {
            int idx = (p * 512 + tid) * 4;
            int m = idx >> 7;
            int k = idx & (KDIM - 1);
            float4 v = make_float4(0.f, 0.f, 0.f, 0.f);
            if (row0 + m < NN) v = *(const float4*)&x[(row0 + m) * KDIM + k];
            *(float4*)&As[m * ASTR + k] = v;
        }
        fill_B<256, 512>(Bs, Wl1, Wr1);
        __syncthreads();
        gemm_mma_epilogue<256>(row0, As, Bs, g_zl, g_zr);
    }
}

// ---------------- CSR scan: A (per-block partials) + BC (offsets applied) ----------------
__global__ void scanA_kernel() {
    __shared__ int sh[256];
    const int t = threadIdx.x;
    const int i = blockIdx.x * 256 + t;
    int v = (i < NN) ? g_deg[i] : 0;
    sh[t] = v;
    __syncthreads();
#pragma unroll
    for (int off = 1; off < 256; off <<= 1) {
        int u = (t >= off) ? sh[t - off] : 0;
        __syncthreads();
        sh[t] += u;
        __syncthreads();
    }
    if (i < NN) g_rowstart[i] = sh[t] - v;        // exclusive local prefix
    if (t == 255) g_bsum[blockIdx.x] = sh[255];   // block total
}

__global__ void scanBC_kernel() {
    __shared__ int sh[256];
    __shared__ int ex[256];
    const int t = threadIdx.x;
    int v = (t < NB) ? g_bsum[t] : 0;
    sh[t] = v;
    __syncthreads();
#pragma unroll
    for (int off = 1; off < 256; off <<= 1) {
        int u = (t >= off) ? sh[t - off] : 0;
        __syncthreads();
        sh[t] += u;
        __syncthreads();
    }
    ex[t] = sh[t] - v;                            // exclusive
    __syncthreads();
    const int boff = ex[blockIdx.x];
    const int i = blockIdx.x * 256 + t;
    if (i < NN) {
        int r = g_rowstart[i] + boff;
        g_rowstart[i] = r;
        g_cursor[i]   = r;
    }
    if (i == 0) g_rowstart[NN] = sh[NB - 1];      // grand total
}

__global__ void fill_kernel(const void* __restrict__ ei) {
    __shared__ int s_nz;
    bool is64 = detect_is64<256, 4>((const int*)ei, &s_nz);
    int e = blockIdx.x * blockDim.x + threadIdx.x;
    if (e < EE) {
        int d = edge_at(ei, is64, (long long)EE + e);
        int s = edge_at(ei, is64, e);
        if ((unsigned)d < NN && (unsigned)s < NN) {
            int pos = atomicAdd(&g_cursor[d], 1);
            g_esrc[pos] = s;
        }
    }
}

// ---------------- K2: layer-1 aggregate fused INTO layer-2 GEMM ----------------
// Each block computes h = relu(mean_agg(zl)+zr+b1) for its 128 rows directly
// into the As smem tile (identical gather to the old agg_epi1), then runs the
// full-K MMA into ul|ur. g_h never exists in global memory.
__global__ __launch_bounds__(512) void gemm2_fused_kernel(const float* __restrict__ Wl2,
                                                          const float* __restrict__ Wr2,
                                                          const float* __restrict__ b1) {
    constexpr int ASTR = KDIM + 8;
    extern __shared__ float smem[];
    float* As = smem;
    float* Bs = smem + 128 * ASTR;
    const int row0 = blockIdx.x * 128;
    const int tid = threadIdx.x;
    const int wid = tid >> 5, lane = tid & 31;
    const int c = lane * 4;

    fill_B<128, 512>(Bs, Wl2, Wr2);   // issue weight loads first

    const float4 bb = *(const float4*)&b1[c];
    // warp w computes rows w*8 .. w*8+7
#pragma unroll 1
    for (int i = 0; i < 8; i++) {
        const int m = wid * 8 + i;
        const int row = row0 + m;
        float4 o = make_float4(0.f, 0.f, 0.f, 0.f);
        if (row < NN) {
            int lo = g_rowstart[row], hi = g_rowstart[row + 1];
            float4 acc = make_float4(0.f, 0.f, 0.f, 0.f);
            int j = lo;
            for (; j + 4 <= hi; j += 4) {
                int s0 = g_esrc[j], s1 = g_esrc[j + 1], s2 = g_esrc[j + 2], s3 = g_esrc[j + 3];
                float4 v0 = *(const float4*)&g_zl[s0 * DHID + c];
                float4 v1 = *(const float4*)&g_zl[s1 * DHID + c];
                float4 v2 = *(const float4*)&g_zl[s2 * DHID + c];
                float4 v3 = *(const float4*)&g_zl[s3 * DHID + c];
                acc.x += (v0.x + v1.x) + (v2.x + v3.x);
                acc.y += (v0.y + v1.y) + (v2.y + v3.y);
                acc.z += (v0.z + v1.z) + (v2.z + v3.z);
                acc.w += (v0.w + v1.w) + (v2.w + v3.w);
            }
            for (; j < hi; j++) {
                int s = g_esrc[j];
                float4 v = *(const float4*)&g_zl[s * DHID + c];
                acc.x += v.x; acc.y += v.y; acc.z += v.z; acc.w += v.w;
            }
            float invd = 1.0f / (float)max(hi - lo, 1);
            float4 r = *(const float4*)&g_zr[row * DHID + c];
            o.x = fmaxf(fmaf(acc.x, invd, r.x + bb.x), 0.f);
            o.y = fmaxf(fmaf(acc.y, invd, r.y + bb.y), 0.f);
            o.z = fmaxf(fmaf(acc.z, invd, r.z + bb.z), 0.f);
            o.w = fmaxf(fmaf(acc.w, invd, r.w + bb.w), 0.f);
        }
        *(float4*)&As[m * ASTR + c] = o;
    }
    __syncthreads();

    gemm_mma_epilogue<128>(row0, As, Bs, g_ul, g_ur);
}

// ---------------- layer-2 aggregate + epilogue -> out; resets g_deg ----------------
__global__ void agg_epi2_kernel(const float* __restrict__ b2, float* __restrict__ out) {
    int gw = (blockIdx.x * blockDim.x + threadIdx.x) >> 5;
    if (gw >= NN) return;
    int lane = threadIdx.x & 31;
    int c = lane * 2;
    int lo = g_rowstart[gw], hi = g_rowstart[gw + 1];

    float2 acc = make_float2(0.f, 0.f);
    int j = lo;
    for (; j + 4 <= hi; j += 4) {
        int s0 = g_esrc[j], s1 = g_esrc[j + 1], s2 = g_esrc[j + 2], s3 = g_esrc[j + 3];
        float2 v0 = *(const float2*)&g_ul[s0 * DOUT + c];
        float2 v1 = *(const float2*)&g_ul[s1 * DOUT + c];
        float2 v2 = *(const float2*)&g_ul[s2 * DOUT + c];
        float2 v3 = *(const float2*)&g_ul[s3 * DOUT + c];
        acc.x += (v0.x + v1.x) + (v2.x + v3.x);
        acc.y += (v0.y + v1.y) + (v2.y + v3.y);
    }
    for (; j < hi; j++) {
        int s = g_esrc[j];
        float2 v = *(const float2*)&g_ul[s * DOUT + c];
        acc.x += v.x; acc.y += v.y;
    }
    float invd = 1.0f / (float)max(hi - lo, 1);
    float2 r  = *(const float2*)&g_ur[gw * DOUT + c];
    float2 bb = *(const float2*)&b2[c];
    float2 o;
    o.x = fmaf(acc.x, invd, r.x + bb.x);
    o.y = fmaf(acc.y, invd, r.y + bb.y);
    *(float2*)&out[gw * DOUT + c] = o;

    if (lane == 0) g_deg[gw] = 0;   // reset for next launch
}

// ---------------- launch (single stream, 6 kernels) ----------------
extern "C" void kernel_launch(void* const* d_in, const int* in_sizes, int n_in,
                              void* d_out, int out_size) {
    const float* x   = (const float*)d_in[0];
    const void*  ei  = d_in[1];                 // int32 OR int64 — detected per-block
    const float* Wl1 = (const float*)d_in[2];
    const float* Wr1 = (const float*)d_in[3];
    const float* b1  = (const float*)d_in[4];
    const float* Wl2 = (const float*)d_in[5];
    const float* Wr2 = (const float*)d_in[6];
    const float* b2  = (const float*)d_in[7];
    float* out = (float*)d_out;

    // Opt-in to >48KB dynamic smem (host-side attribute, capture-legal, idempotent).
    cudaFuncSetAttribute(gemm1_hist_kernel,  cudaFuncAttributeMaxDynamicSharedMemorySize, SMEM_F1);
    cudaFuncSetAttribute(gemm2_fused_kernel, cudaFuncAttributeMaxDynamicSharedMemorySize, SMEM_F2);

    // K1: layer-1 fused GEMM with histogram blocks interleaved
    gemm1_hist_kernel<<<K1_GRID, 512, SMEM_F1>>>(x, Wl1, Wr1, ei);

    // CSR finish
    scanA_kernel<<<NB, 256>>>();
    scanBC_kernel<<<NB, 256>>>();
    fill_kernel<<<(EE + 255) / 256, 256>>>(ei);

    // K2: layer-1 aggregate (into smem) + layer-2 GEMM
    gemm2_fused_kernel<<<GEMM_GRID, 512, SMEM_F2>>>(Wl2, Wr2, b1);

    // layer-2 aggregate + epilogue
    agg_epi2_kernel<<<(NN * 32 + 255) / 256, 256>>>(b2, out);
}

// round 16
// speedup vs baseline: 1.1616x; 1.1616x over previous
#include <cuda_runtime.h>
#include <cstdint>

#define NN 50000
#define EE 800000
#define KDIM 128
#define DHID 128
#define DOUT 64
#define NB   ((NN + 255) / 256)   // 196 scan blocks

// ---------------- scratch (device globals; no allocs allowed) ----------------
// g_deg relies on static zero-init for the FIRST call; every launch re-zeroes
// it at the tail of agg_epi2 (after its last read in scanA).
__device__ int g_deg[NN];
__device__ int g_rowstart[NN + 1];
__device__ int g_cursor[NN];
__device__ int g_esrc[EE];
__device__ int g_bsum[NB];

__device__ float g_zl[NN * DHID];  // x @ W_l1  (gets aggregated)
__device__ float g_zr[NN * DHID];  // x @ W_r1  (self term)
__device__ float g_h [NN * DHID];  // layer-1 output
__device__ float g_ul[NN * DOUT];  // h @ W_l2  (gets aggregated)
__device__ float g_ur[NN * DOUT];  // h @ W_r2  (self term)

// ---------------- per-block edge dtype detection (no global state) ----------------
template <int THREADS, int PER>
__device__ __forceinline__ bool detect_is64(const int* __restrict__ ei32, int* s_nz) {
    if (threadIdx.x == 0) *s_nz = 0;
    __syncthreads();
    bool nz = false;
#pragma unroll
    for (int p = 0; p < PER; p++) {
        int i = threadIdx.x + p * THREADS;      // i in [0, 1024)
        nz |= (ei32[2 * i + 1] != 0);
    }
    if (__ballot_sync(0xffffffffu, nz) && (threadIdx.x & 31) == 0) *s_nz = 1;
    __syncthreads();
    return (*s_nz == 0);
}

__device__ __forceinline__ int edge_at(const void* ei, bool is64, long long idx) {
    return is64 ? (int)((const long long*)ei)[idx] : ((const int*)ei)[idx];
}

// ---------------- tf32 helpers ----------------
__device__ __forceinline__ float tf32_hi(float v) {
    uint32_t r;
    asm("cvt.rna.tf32.f32 %0, %1;" : "=r"(r) : "f"(v));
    return __uint_as_float(r);
}

__device__ __forceinline__ void mma_tf32(float d[4], const uint32_t a[4], const uint32_t b[2]) {
    asm volatile(
        "mma.sync.aligned.m16n8k8.row.col.f32.tf32.tf32.f32 "
        "{%0,%1,%2,%3}, {%4,%5,%6,%7}, {%8,%9}, {%0,%1,%2,%3};\n"
        : "+f"(d[0]), "+f"(d[1]), "+f"(d[2]), "+f"(d[3])
        : "r"(a[0]), "r"(a[1]), "r"(a[2]), "r"(a[3]),
          "r"(b[0]), "r"(b[1]));
}

// ---------------- shared GEMM compute: As/Bs smem-resident, full K ----------------
template <int BN>
__device__ __forceinline__
void gemm_mma_epilogue(int row0, const float* As, const float* Bs,
                       float* __restrict__ C1, float* __restrict__ C2) {
    constexpr int HALF = BN / 2;
    constexpr int WN = BN / 4;
    constexpr int NT = WN / 8;
    constexpr int ASTR = KDIM + 8;
    constexpr int BSTR = BN + 8;

    const int tid = threadIdx.x;
    const int wid = tid >> 5, lane = tid & 31;
    const int gq = lane >> 2, tg = lane & 3;
    const int warp_m = wid & 3;
    const int warp_n = wid >> 2;

    float acc[2][NT][4];
#pragma unroll
    for (int mt = 0; mt < 2; mt++)
#pragma unroll
        for (int nt = 0; nt < NT; nt++)
#pragma unroll
            for (int r = 0; r < 4; r++) acc[mt][nt][r] = 0.0f;

#pragma unroll 1
    for (int ks = 0; ks < KDIM / 8; ks++) {
        const int kk = ks * 8;
        uint32_t ah[2][4], al[2][4];
#pragma unroll
        for (int mt = 0; mt < 2; mt++) {
            int r = warp_m * 32 + mt * 16 + gq;
            float f0 = As[(r    ) * ASTR + kk + tg];
            float f1 = As[(r + 8) * ASTR + kk + tg];
            float f2 = As[(r    ) * ASTR + kk + tg + 4];
            float f3 = As[(r + 8) * ASTR + kk + tg + 4];
            float h0 = tf32_hi(f0), h1 = tf32_hi(f1), h2 = tf32_hi(f2), h3 = tf32_hi(f3);
            ah[mt][0] = __float_as_uint(h0); al[mt][0] = __float_as_uint(f0 - h0);
            ah[mt][1] = __float_as_uint(h1); al[mt][1] = __float_as_uint(f1 - h1);
            ah[mt][2] = __float_as_uint(h2); al[mt][2] = __float_as_uint(f2 - h2);
            ah[mt][3] = __float_as_uint(h3); al[mt][3] = __float_as_uint(f3 - h3);
        }
#pragma unroll
        for (int nt = 0; nt < NT; nt++) {
            int c = warp_n * WN + nt * 8 + gq;
            float g0 = Bs[(kk + tg    ) * BSTR + c];
            float g1 = Bs[(kk + tg + 4) * BSTR + c];
            float h0 = tf32_hi(g0), h1 = tf32_hi(g1);
            uint32_t bh[2], bl[2];
            bh[0] = __float_as_uint(h0); bl[0] = __float_as_uint(g0 - h0);
            bh[1] = __float_as_uint(h1); bl[1] = __float_as_uint(g1 - h1);
#pragma unroll
            for (int mt = 0; mt < 2; mt++) {
                mma_tf32(acc[mt][nt], al[mt], bh);  // lo*hi
                mma_tf32(acc[mt][nt], ah[mt], bl);  // hi*lo
                mma_tf32(acc[mt][nt], ah[mt], bh);  // hi*hi
            }
        }
    }

#pragma unroll
    for (int mt = 0; mt < 2; mt++) {
        int r = row0 + warp_m * 32 + mt * 16 + gq;
#pragma unroll
        for (int nt = 0; nt < NT; nt++) {
            int c = warp_n * WN + nt * 8 + 2 * tg;
            float* Cp = (c < HALF) ? C1 : C2;
            int cc = (c < HALF) ? c : c - HALF;
            if (r < NN) {
                float2 v = make_float2(acc[mt][nt][0], acc[mt][nt][1]);
                *(float2*)&Cp[r * HALF + cc] = v;
            }
            if (r + 8 < NN) {
                float2 v = make_float2(acc[mt][nt][2], acc[mt][nt][3]);
                *(float2*)&Cp[(r + 8) * HALF + cc] = v;
            }
        }
    }
}

// B-fill helper: Bs[KDIM][BN+8] from B1|B2 halves.
template <int BN, int THREADS>
__device__ __forceinline__
void fill_B(float* Bs, const float* __restrict__ B1, const float* __restrict__ B2) {
    constexpr int HALF = BN / 2;
    constexpr int BSTR = BN + 8;
    const int tid = threadIdx.x;
#pragma unroll
    for (int p = 0; p < (KDIM * BN) / (THREADS * 4); p++) {
        int idx = (p * THREADS + tid) * 4;
        int k = idx / BN;
        int n = idx % BN;
        const float* src = (n < HALF) ? &B1[k * HALF + n] : &B2[k * HALF + (n - HALF)];
        *(float4*)&Bs[k * BSTR + n] = *(const float4*)src;
    }
}

#define SMEM_F1 ((128 * (KDIM + 8) + KDIM * (256 + 8)) * 4)   // 204800 B
#define SMEM_F2 ((128 * (KDIM + 8) + KDIM * (128 + 8)) * 4)   // 139264 B

#define GEMM_GRID ((NN + 127) / 128)          // 391 gemm blocks

// ---------------- K1: layer-1 fused GEMM; histogram as per-block TAIL work ----------------
// No dedicated hist blocks (R14's 128 hist blocks each held the 200KB smem
// reservation = ~1 extra full wave). Each gemm block grid-strides its share of
// E after its epilogue; completion skew overlaps tails with other blocks' MMAs.
__global__ __launch_bounds__(512) void gemm1_hist_kernel(const float* __restrict__ x,
                                                         const float* __restrict__ Wl1,
                                                         const float* __restrict__ Wr1,
                                                         const void* __restrict__ ei) {
    constexpr int ASTR = KDIM + 8;
    extern __shared__ float smem[];
    float* As = smem;
    float* Bs = smem + 128 * ASTR;
    const int row0 = blockIdx.x * 128;
    const int tid = threadIdx.x;

    // A fill: x rows
#pragma unroll
    for (int p = 0; p < (128 * KDIM) / (512 * 4); p++) {
        int idx = (p * 512 + tid) * 4;
        int m = idx >> 7;
        int k = idx & (KDIM - 1);
        float4 v = make_float4(0.f, 0.f, 0.f, 0.f);
        if (row0 + m < NN) v = *(const float4*)&x[(row0 + m) * KDIM + k];
        *(float4*)&As[m * ASTR + k] = v;
    }
    fill_B<256, 512>(Bs, Wl1, Wr1);
    __syncthreads();
    gemm_mma_epilogue<256>(row0, As, Bs, g_zl, g_zr);

    // ---- histogram tail: this block's slice of the edge list ----
    __shared__ int s_nz;
    bool is64 = detect_is64<512, 2>((const int*)ei, &s_nz);
    const int stride = GEMM_GRID * 512;
    for (int e = blockIdx.x * 512 + tid; e < EE; e += stride) {
        int d = edge_at(ei, is64, (long long)EE + e);
        if ((unsigned)d < NN) atomicAdd(&g_deg[d], 1);
    }
}

// ---------------- CSR scan: A (per-block partials) + BC (offsets applied) ----------------
__global__ void scanA_kernel() {
    __shared__ int sh[256];
    const int t = threadIdx.x;
    const int i = blockIdx.x * 256 + t;
    int v = (i < NN) ? g_deg[i] : 0;
    sh[t] = v;
    __syncthreads();
#pragma unroll
    for (int off = 1; off < 256; off <<= 1) {
        int u = (t >= off) ? sh[t - off] : 0;
        __syncthreads();
        sh[t] += u;
        __syncthreads();
    }
    if (i < NN) g_rowstart[i] = sh[t] - v;        // exclusive local prefix
    if (t == 255) g_bsum[blockIdx.x] = sh[255];   // block total
}

__global__ void scanBC_kernel() {
    __shared__ int sh[256];
    __shared__ int ex[256];
    const int t = threadIdx.x;
    int v = (t < NB) ? g_bsum[t] : 0;
    sh[t] = v;
    __syncthreads();
#pragma unroll
    for (int off = 1; off < 256; off <<= 1) {
        int u = (t >= off) ? sh[t - off] : 0;
        __syncthreads();
        sh[t] += u;
        __syncthreads();
    }
    ex[t] = sh[t] - v;                            // exclusive
    __syncthreads();
    const int boff = ex[blockIdx.x];
    const int i = blockIdx.x * 256 + t;
    if (i < NN) {
        int r = g_rowstart[i] + boff;
        g_rowstart[i] = r;
        g_cursor[i]   = r;
    }
    if (i == 0) g_rowstart[NN] = sh[NB - 1];      // grand total
}

__global__ void fill_kernel(const void* __restrict__ ei) {
    __shared__ int s_nz;
    bool is64 = detect_is64<256, 4>((const int*)ei, &s_nz);
    int e = blockIdx.x * blockDim.x + threadIdx.x;
    if (e < EE) {
        int d = edge_at(ei, is64, (long long)EE + e);
        int s = edge_at(ei, is64, e);
        if ((unsigned)d < NN && (unsigned)s < NN) {
            int pos = atomicAdd(&g_cursor[d], 1);
            g_esrc[pos] = s;
        }
    }
}

// ---------------- layer-1 aggregate + epilogue (standalone, high occupancy) ----------------
__global__ void agg_epi1_kernel(const float* __restrict__ b1) {
    int gw = (blockIdx.x * blockDim.x + threadIdx.x) >> 5;
    if (gw >= NN) return;
    int lane = threadIdx.x & 31;
    int c = lane * 4;
    int lo = g_rowstart[gw], hi = g_rowstart[gw + 1];

    float4 acc = make_float4(0.f, 0.f, 0.f, 0.f);
    int j = lo;
    for (; j + 4 <= hi; j += 4) {
        int s0 = g_esrc[j], s1 = g_esrc[j + 1], s2 = g_esrc[j + 2], s3 = g_esrc[j + 3];
        float4 v0 = *(const float4*)&g_zl[s0 * DHID + c];
        float4 v1 = *(const float4*)&g_zl[s1 * DHID + c];
        float4 v2 = *(const float4*)&g_zl[s2 * DHID + c];
        float4 v3 = *(const float4*)&g_zl[s3 * DHID + c];
        acc.x += (v0.x + v1.x) + (v2.x + v3.x);
        acc.y += (v0.y + v1.y) + (v2.y + v3.y);
        acc.z += (v0.z + v1.z) + (v2.z + v3.z);
        acc.w += (v0.w + v1.w) + (v2.w + v3.w);
    }
    for (; j < hi; j++) {
        int s = g_esrc[j];
        float4 v = *(const float4*)&g_zl[s * DHID + c];
        acc.x += v.x; acc.y += v.y; acc.z += v.z; acc.w += v.w;
    }
    float invd = 1.0f / (float)max(hi - lo, 1);
    float4 r  = *(const float4*)&g_zr[gw * DHID + c];
    float4 bb = *(const float4*)&b1[c];
    float4 o;
    o.x = fmaxf(fmaf(acc.x, invd, r.x + bb.x), 0.f);
    o.y = fmaxf(fmaf(acc.y, invd, r.y + bb.y), 0.f);
    o.z = fmaxf(fmaf(acc.z, invd, r.z + bb.z), 0.f);
    o.w = fmaxf(fmaf(acc.w, invd, r.w + bb.w), 0.f);
    *(float4*)&g_h[gw * DHID + c] = o;
}

// ---------------- layer-2 fused GEMM ----------------
__global__ __launch_bounds__(512) void gemm_f2_kernel(const float* __restrict__ Wl2,
                                                      const float* __restrict__ Wr2) {
    constexpr int ASTR = KDIM + 8;
    extern __shared__ float smem[];
    float* As = smem;
    float* Bs = smem + 128 * ASTR;
    const int row0 = blockIdx.x * 128;
    const int tid = threadIdx.x;
#pragma unroll
    for (int p = 0; p < (128 * KDIM) / (512 * 4); p++) {
        int idx = (p * 512 + tid) * 4;
        int m = idx >> 7;
        int k = idx & (KDIM - 1);
        float4 v = make_float4(0.f, 0.f, 0.f, 0.f);
        if (row0 + m < NN) v = *(const float4*)&g_h[(row0 + m) * KDIM + k];
        *(float4*)&As[m * ASTR + k] = v;
    }
    fill_B<128, 512>(Bs, Wl2, Wr2);
    __syncthreads();
    gemm_mma_epilogue<128>(row0, As, Bs, g_ul, g_ur);
}

// ---------------- layer-2 aggregate + epilogue -> out; resets g_deg ----------------
__global__ void agg_epi2_kernel(const float* __restrict__ b2, float* __restrict__ out) {
    int gw = (blockIdx.x * blockDim.x + threadIdx.x) >> 5;
    if (gw >= NN) return;
    int lane = threadIdx.x & 31;
    int c = lane * 2;
    int lo = g_rowstart[gw], hi = g_rowstart[gw + 1];

    float2 acc = make_float2(0.f, 0.f);
    int j = lo;
    for (; j + 4 <= hi; j += 4) {
        int s0 = g_esrc[j], s1 = g_esrc[j + 1], s2 = g_esrc[j + 2], s3 = g_esrc[j + 3];
        float2 v0 = *(const float2*)&g_ul[s0 * DOUT + c];
        float2 v1 = *(const float2*)&g_ul[s1 * DOUT + c];
        float2 v2 = *(const float2*)&g_ul[s2 * DOUT + c];
        float2 v3 = *(const float2*)&g_ul[s3 * DOUT + c];
        acc.x += (v0.x + v1.x) + (v2.x + v3.x);
        acc.y += (v0.y + v1.y) + (v2.y + v3.y);
    }
    for (; j < hi; j++) {
        int s = g_esrc[j];
        float2 v = *(const float2*)&g_ul[s * DOUT + c];
        acc.x += v.x; acc.y += v.y;
    }
    float invd = 1.0f / (float)max(hi - lo, 1);
    float2 r  = *(const float2*)&g_ur[gw * DOUT + c];
    float2 bb = *(const float2*)&b2[c];
    float2 o;
    o.x = fmaf(acc.x, invd, r.x + bb.x);
    o.y = fmaf(acc.y, invd, r.y + bb.y);
    *(float2*)&out[gw * DOUT + c] = o;

    if (lane == 0) g_deg[gw] = 0;   // reset for next launch
}

// ---------------- launch (single stream, 7 kernels) ----------------
extern "C" void kernel_launch(void* const* d_in, const int* in_sizes, int n_in,
                              void* d_out, int out_size) {
    const float* x   = (const float*)d_in[0];
    const void*  ei  = d_in[1];                 // int32 OR int64 — detected per-block
    const float* Wl1 = (const float*)d_in[2];
    const float* Wr1 = (const float*)d_in[3];
    const float* b1  = (const float*)d_in[4];
    const float* Wl2 = (const float*)d_in[5];
    const float* Wr2 = (const float*)d_in[6];
    const float* b2  = (const float*)d_in[7];
    float* out = (float*)d_out;

    // Opt-in to >48KB dynamic smem (host-side attribute, capture-legal, idempotent).
    cudaFuncSetAttribute(gemm1_hist_kernel, cudaFuncAttributeMaxDynamicSharedMemorySize, SMEM_F1);
    cudaFuncSetAttribute(gemm_f2_kernel,    cudaFuncAttributeMaxDynamicSharedMemorySize, SMEM_F2);

    // K1: layer-1 fused GEMM with per-block histogram tails
    gemm1_hist_kernel<<<GEMM_GRID, 512, SMEM_F1>>>(x, Wl1, Wr1, ei);

    // CSR finish
    scanA_kernel<<<NB, 256>>>();
    scanBC_kernel<<<NB, 256>>>();
    fill_kernel<<<(EE + 255) / 256, 256>>>(ei);

    // layer-1 aggregate + epilogue (standalone, high occupancy)
    agg_epi1_kernel<<<(NN * 32 + 255) / 256, 256>>>(b1);

    // layer-2 fused projections + aggregation
    gemm_f2_kernel<<<GEMM_GRID, 512, SMEM_F2>>>(Wl2, Wr2);
    agg_epi2_kernel<<<(NN * 32 + 255) / 256, 256>>>(b2, out);
}

// round 17
// speedup vs baseline: 1.2003x; 1.0333x over previous
#include <cuda_runtime.h>
#include <cstdint>

#define NN 50000
#define EE 800000
#define KDIM 128
#define DHID 128
#define DOUT 64
#define NB   ((NN + 255) / 256)   // 196 scan blocks

// ---------------- scratch (device globals; no allocs allowed) ----------------
// g_deg relies on static zero-init for the FIRST call; every launch re-zeroes
// it at the tail of agg_epi2 (after its last read in scanA).
__device__ int g_deg[NN];
__device__ int g_rowstart[NN + 1];
__device__ int g_cursor[NN];
__device__ int g_esrc[EE];
__device__ int g_bsum[NB];

__device__ float g_zl[NN * DHID];  // x @ W_l1  (gets aggregated)
__device__ float g_zr[NN * DHID];  // x @ W_r1  (self term)
__device__ float g_h [NN * DHID];  // layer-1 output
__device__ float g_ul[NN * DOUT];  // h @ W_l2  (gets aggregated)
__device__ float g_ur[NN * DOUT];  // h @ W_r2  (self term)

// ---------------- per-block edge dtype detection (no global state) ----------------
template <int THREADS, int PER>
__device__ __forceinline__ bool detect_is64(const int* __restrict__ ei32, int* s_nz) {
    if (threadIdx.x == 0) *s_nz = 0;
    __syncthreads();
    bool nz = false;
#pragma unroll
    for (int p = 0; p < PER; p++) {
        int i = threadIdx.x + p * THREADS;      // i in [0, 1024)
        nz |= (ei32[2 * i + 1] != 0);
    }
    if (__ballot_sync(0xffffffffu, nz) && (threadIdx.x & 31) == 0) *s_nz = 1;
    __syncthreads();
    return (*s_nz == 0);
}

__device__ __forceinline__ int edge_at(const void* ei, bool is64, long long idx) {
    return is64 ? (int)((const long long*)ei)[idx] : ((const int*)ei)[idx];
}

// ---------------- tf32 helpers ----------------
__device__ __forceinline__ float tf32_hi(float v) {
    uint32_t r;
    asm("cvt.rna.tf32.f32 %0, %1;" : "=r"(r) : "f"(v));
    return __uint_as_float(r);
}

__device__ __forceinline__ void mma_tf32(float d[4], const uint32_t a[4], const uint32_t b[2]) {
    asm volatile(
        "mma.sync.aligned.m16n8k8.row.col.f32.tf32.tf32.f32 "
        "{%0,%1,%2,%3}, {%4,%5,%6,%7}, {%8,%9}, {%0,%1,%2,%3};\n"
        : "+f"(d[0]), "+f"(d[1]), "+f"(d[2]), "+f"(d[3])
        : "r"(a[0]), "r"(a[1]), "r"(a[2]), "r"(a[3]),
          "r"(b[0]), "r"(b[1]));
}

// ---------------- single-output GEMM block: BM=64, 256 threads, full-K resident ----------------
// C[M x BN] = A[M x 128] @ B[128 x BN] for ONE output matrix.
// 8 warps as 2(m) x 4(n); warp tile 32 x (BN/4). acc = 2 x (BN/32) x 4 regs.
// Small regs+smem -> 2-3 blocks/SM so fills overlap other blocks' MMAs.
template <int BN>
__device__ __forceinline__
void gemm_one_body(int gid, const float* __restrict__ A,
                   const float* __restrict__ B, float* __restrict__ C) {
    constexpr int BM = 64;
    constexpr int THREADS = 256;
    constexpr int WN = BN / 4;
    constexpr int NT = WN / 8;
    constexpr int ASTR = KDIM + 8;   // 136
    constexpr int BSTR = BN + 8;

    extern __shared__ float smem[];
    float* As = smem;                 // [BM][ASTR]
    float* Bs = smem + BM * ASTR;     // [KDIM][BSTR]

    const int tid = threadIdx.x;
    const int wid = tid >> 5, lane = tid & 31;
    const int gq = lane >> 2, tg = lane & 3;
    const int warp_m = wid & 1;                // 2 m-warps x 32 rows
    const int warp_n = wid >> 1;               // 4 n-warps x WN cols
    const int row0 = gid * BM;

    // fill A (BM x KDIM)
#pragma unroll
    for (int p = 0; p < (BM * KDIM) / (THREADS * 4); p++) {
        int idx = (p * THREADS + tid) * 4;
        int m = idx >> 7;
        int k = idx & (KDIM - 1);
        float4 v = make_float4(0.f, 0.f, 0.f, 0.f);
        if (row0 + m < NN) v = *(const float4*)&A[(row0 + m) * KDIM + k];
        *(float4*)&As[m * ASTR + k] = v;
    }
    // fill B (KDIM x BN)
#pragma unroll
    for (int p = 0; p < (KDIM * BN) / (THREADS * 4); p++) {
        int idx = (p * THREADS + tid) * 4;
        int k = idx / BN;
        int n = idx % BN;
        *(float4*)&Bs[k * BSTR + n] = *(const float4*)&B[k * BN + n];
    }
    __syncthreads();

    float acc[2][NT][4];
#pragma unroll
    for (int mt = 0; mt < 2; mt++)
#pragma unroll
        for (int nt = 0; nt < NT; nt++)
#pragma unroll
            for (int r = 0; r < 4; r++) acc[mt][nt][r] = 0.0f;

#pragma unroll 1
    for (int ks = 0; ks < KDIM / 8; ks++) {
        const int kk = ks * 8;
        uint32_t ah[2][4], al[2][4];
#pragma unroll
        for (int mt = 0; mt < 2; mt++) {
            int r = warp_m * 32 + mt * 16 + gq;
            float f0 = As[(r    ) * ASTR + kk + tg];
            float f1 = As[(r + 8) * ASTR + kk + tg];
            float f2 = As[(r    ) * ASTR + kk + tg + 4];
            float f3 = As[(r + 8) * ASTR + kk + tg + 4];
            float h0 = tf32_hi(f0), h1 = tf32_hi(f1), h2 = tf32_hi(f2), h3 = tf32_hi(f3);
            ah[mt][0] = __float_as_uint(h0); al[mt][0] = __float_as_uint(f0 - h0);
            ah[mt][1] = __float_as_uint(h1); al[mt][1] = __float_as_uint(f1 - h1);
            ah[mt][2] = __float_as_uint(h2); al[mt][2] = __float_as_uint(f2 - h2);
            ah[mt][3] = __float_as_uint(h3); al[mt][3] = __float_as_uint(f3 - h3);
        }
#pragma unroll
        for (int nt = 0; nt < NT; nt++) {
            int c = warp_n * WN + nt * 8 + gq;
            float g0 = Bs[(kk + tg    ) * BSTR + c];
            float g1 = Bs[(kk + tg + 4) * BSTR + c];
            float h0 = tf32_hi(g0), h1 = tf32_hi(g1);
            uint32_t bh[2], bl[2];
            bh[0] = __float_as_uint(h0); bl[0] = __float_as_uint(g0 - h0);
            bh[1] = __float_as_uint(h1); bl[1] = __float_as_uint(g1 - h1);
#pragma unroll
            for (int mt = 0; mt < 2; mt++) {
                mma_tf32(acc[mt][nt], al[mt], bh);  // lo*hi
                mma_tf32(acc[mt][nt], ah[mt], bl);  // hi*lo
                mma_tf32(acc[mt][nt], ah[mt], bh);  // hi*hi
            }
        }
    }

    // epilogue: c0/c1 at (row, 2*tg), c2/c3 at (row+8, 2*tg)
#pragma unroll
    for (int mt = 0; mt < 2; mt++) {
        int r = row0 + warp_m * 32 + mt * 16 + gq;
#pragma unroll
        for (int nt = 0; nt < NT; nt++) {
            int c = warp_n * WN + nt * 8 + 2 * tg;
            if (r < NN) {
                float2 v = make_float2(acc[mt][nt][0], acc[mt][nt][1]);
                *(float2*)&C[r * BN + c] = v;
            }
            if (r + 8 < NN) {
                float2 v = make_float2(acc[mt][nt][2], acc[mt][nt][3]);
                *(float2*)&C[(r + 8) * BN + c] = v;
            }
        }
    }
}

#define NBLK64 ((NN + 63) / 64)               // 782 row-blocks
#define GEMM_GRID2 (2 * NBLK64)               // 1564 blocks (out = bx & 1)
#define SMEM_G1 ((64 * (KDIM + 8) + KDIM * (128 + 8)) * 4)   // 104448 B -> 2 blocks/SM
#define SMEM_G2 ((64 * (KDIM + 8) + KDIM * (64 + 8)) * 4)    //  71680 B -> 3 blocks/SM

// ---------------- K1: layer-1 GEMMs (zl, zr) + histogram tail ----------------
__global__ __launch_bounds__(256) void gemm1_hist_kernel(const float* __restrict__ x,
                                                         const float* __restrict__ Wl1,
                                                         const float* __restrict__ Wr1,
                                                         const void* __restrict__ ei) {
    const int out = blockIdx.x & 1;            // interleaved: zl/zr pairs share x rows in L2
    const int gid = blockIdx.x >> 1;
    gemm_one_body<128>(gid, x, out ? Wr1 : Wl1, out ? g_zr : g_zl);

    // histogram tail: this block's slice of the edge list
    __shared__ int s_nz;
    bool is64 = detect_is64<256, 4>((const int*)ei, &s_nz);
    const int stride = GEMM_GRID2 * 256;
    for (int e = blockIdx.x * 256 + threadIdx.x; e < EE; e += stride) {
        int d = edge_at(ei, is64, (long long)EE + e);
        if ((unsigned)d < NN) atomicAdd(&g_deg[d], 1);
    }
}

// ---------------- CSR scan: A (per-block partials) + BC (offsets applied) ----------------
__global__ void scanA_kernel() {
    __shared__ int sh[256];
    const int t = threadIdx.x;
    const int i = blockIdx.x * 256 + t;
    int v = (i < NN) ? g_deg[i] : 0;
    sh[t] = v;
    __syncthreads();
#pragma unroll
    for (int off = 1; off < 256; off <<= 1) {
        int u = (t >= off) ? sh[t - off] : 0;
        __syncthreads();
        sh[t] += u;
        __syncthreads();
    }
    if (i < NN) g_rowstart[i] = sh[t] - v;        // exclusive local prefix
    if (t == 255) g_bsum[blockIdx.x] = sh[255];   // block total
}

__global__ void scanBC_kernel() {
    __shared__ int sh[256];
    __shared__ int ex[256];
    const int t = threadIdx.x;
    int v = (t < NB) ? g_bsum[t] : 0;
    sh[t] = v;
    __syncthreads();
#pragma unroll
    for (int off = 1; off < 256; off <<= 1) {
        int u = (t >= off) ? sh[t - off] : 0;
        __syncthreads();
        sh[t] += u;
        __syncthreads();
    }
    ex[t] = sh[t] - v;                            // exclusive
    __syncthreads();
    const int boff = ex[blockIdx.x];
    const int i = blockIdx.x * 256 + t;
    if (i < NN) {
        int r = g_rowstart[i] + boff;
        g_rowstart[i] = r;
        g_cursor[i]   = r;
    }
    if (i == 0) g_rowstart[NN] = sh[NB - 1];      // grand total
}

__global__ void fill_kernel(const void* __restrict__ ei) {
    __shared__ int s_nz;
    bool is64 = detect_is64<256, 4>((const int*)ei, &s_nz);
    int e = blockIdx.x * blockDim.x + threadIdx.x;
    if (e < EE) {
        int d = edge_at(ei, is64, (long long)EE + e);
        int s = edge_at(ei, is64, e);
        if ((unsigned)d < NN && (unsigned)s < NN) {
            int pos = atomicAdd(&g_cursor[d], 1);
            g_esrc[pos] = s;
        }
    }
}

// ---------------- layer-1 aggregate + epilogue (standalone, high occupancy) ----------------
__global__ void agg_epi1_kernel(const float* __restrict__ b1) {
    int gw = (blockIdx.x * blockDim.x + threadIdx.x) >> 5;
    if (gw >= NN) return;
    int lane = threadIdx.x & 31;
    int c = lane * 4;
    int lo = g_rowstart[gw], hi = g_rowstart[gw + 1];

    float4 acc = make_float4(0.f, 0.f, 0.f, 0.f);
    int j = lo;
    for (; j + 4 <= hi; j += 4) {
        int s0 = g_esrc[j], s1 = g_esrc[j + 1], s2 = g_esrc[j + 2], s3 = g_esrc[j + 3];
        float4 v0 = *(const float4*)&g_zl[s0 * DHID + c];
        float4 v1 = *(const float4*)&g_zl[s1 * DHID + c];
        float4 v2 = *(const float4*)&g_zl[s2 * DHID + c];
        float4 v3 = *(const float4*)&g_zl[s3 * DHID + c];
        acc.x += (v0.x + v1.x) + (v2.x + v3.x);
        acc.y += (v0.y + v1.y) + (v2.y + v3.y);
        acc.z += (v0.z + v1.z) + (v2.z + v3.z);
        acc.w += (v0.w + v1.w) + (v2.w + v3.w);
    }
    for (; j < hi; j++) {
        int s = g_esrc[j];
        float4 v = *(const float4*)&g_zl[s * DHID + c];
        acc.x += v.x; acc.y += v.y; acc.z += v.z; acc.w += v.w;
    }
    float invd = 1.0f / (float)max(hi - lo, 1);
    float4 r  = *(const float4*)&g_zr[gw * DHID + c];
    float4 bb = *(const float4*)&b1[c];
    float4 o;
    o.x = fmaxf(fmaf(acc.x, invd, r.x + bb.x), 0.f);
    o.y = fmaxf(fmaf(acc.y, invd, r.y + bb.y), 0.f);
    o.z = fmaxf(fmaf(acc.z, invd, r.z + bb.z), 0.f);
    o.w = fmaxf(fmaf(acc.w, invd, r.w + bb.w), 0.f);
    *(float4*)&g_h[gw * DHID + c] = o;
}

// ---------------- layer-2 GEMMs (ul, ur) ----------------
__global__ __launch_bounds__(256) void gemm_f2_kernel(const float* __restrict__ Wl2,
                                                      const float* __restrict__ Wr2) {
    const int out = blockIdx.x & 1;
    const int gid = blockIdx.x >> 1;
    gemm_one_body<64>(gid, g_h, out ? Wr2 : Wl2, out ? g_ur : g_ul);
}

// ---------------- layer-2 aggregate + epilogue -> out; resets g_deg ----------------
__global__ void agg_epi2_kernel(const float* __restrict__ b2, float* __restrict__ out) {
    int gw = (blockIdx.x * blockDim.x + threadIdx.x) >> 5;
    if (gw >= NN) return;
    int lane = threadIdx.x & 31;
    int c = lane * 2;
    int lo = g_rowstart[gw], hi = g_rowstart[gw + 1];

    float2 acc = make_float2(0.f, 0.f);
    int j = lo;
    for (; j + 4 <= hi; j += 4) {
        int s0 = g_esrc[j], s1 = g_esrc[j + 1], s2 = g_esrc[j + 2], s3 = g_esrc[j + 3];
        float2 v0 = *(const float2*)&g_ul[s0 * DOUT + c];
        float2 v1 = *(const float2*)&g_ul[s1 * DOUT + c];
        float2 v2 = *(const float2*)&g_ul[s2 * DOUT + c];
        float2 v3 = *(const float2*)&g_ul[s3 * DOUT + c];
        acc.x += (v0.x + v1.x) + (v2.x + v3.x);
        acc.y += (v0.y + v1.y) + (v2.y + v3.y);
    }
    for (; j < hi; j++) {
        int s = g_esrc[j];
        float2 v = *(const float2*)&g_ul[s * DOUT + c];
        acc.x += v.x; acc.y += v.y;
    }
    float invd = 1.0f / (float)max(hi - lo, 1);
    float2 r  = *(const float2*)&g_ur[gw * DOUT + c];
    float2 bb = *(const float2*)&b2[c];
    float2 o;
    o.x = fmaf(acc.x, invd, r.x + bb.x);
    o.y = fmaf(acc.y, invd, r.y + bb.y);
    *(float2*)&out[gw * DOUT + c] = o;

    if (lane == 0) g_deg[gw] = 0;   // reset for next launch
}

// ---------------- launch (single stream, 7 kernels) ----------------
extern "C" void kernel_launch(void* const* d_in, const int* in_sizes, int n_in,
                              void* d_out, int out_size) {
    const float* x   = (const float*)d_in[0];
    const void*  ei  = d_in[1];                 // int32 OR int64 — detected per-block
    const float* Wl1 = (const float*)d_in[2];
    const float* Wr1 = (const float*)d_in[3];
    const float* b1  = (const float*)d_in[4];
    const float* Wl2 = (const float*)d_in[5];
    const float* Wr2 = (const float*)d_in[6];
    const float* b2  = (const float*)d_in[7];
    float* out = (float*)d_out;

    // Opt-in to >48KB dynamic smem (host-side attribute, capture-legal, idempotent).
    cudaFuncSetAttribute(gemm1_hist_kernel, cudaFuncAttributeMaxDynamicSharedMemorySize, SMEM_G1);
    cudaFuncSetAttribute(gemm_f2_kernel,    cudaFuncAttributeMaxDynamicSharedMemorySize, SMEM_G2);

    // K1: layer-1 GEMMs (BM=64, 2 blocks/SM) with per-block histogram tails
    gemm1_hist_kernel<<<GEMM_GRID2, 256, SMEM_G1>>>(x, Wl1, Wr1, ei);

    // CSR finish
    scanA_kernel<<<NB, 256>>>();
    scanBC_kernel<<<NB, 256>>>();
    fill_kernel<<<(EE + 255) / 256, 256>>>(ei);

    // layer-1 aggregate + epilogue (standalone, high occupancy)
    agg_epi1_kernel<<<(NN * 32 + 255) / 256, 256>>>(b1);

    // layer-2 GEMMs (BM=64, 3 blocks/SM) + aggregation
    gemm_f2_kernel<<<GEMM_GRID2, 256, SMEM_G2>>>(Wl2, Wr2);
    agg_epi2_kernel<<<(NN * 32 + 255) / 256, 256>>>(b2, out);
}